// round 10
// baseline (speedup 1.0000x reference)
#include <cuda_runtime.h>
#include <math.h>
#include <stdint.h>

// ---------------- problem constants ----------------
#define T_TOK   2048
#define DM      1024
#define HM      512
#define ER      64
#define TOPK    6
#define ES      2
#define NGRP    (ER + ES)
#define NPAIR_R (T_TOK * TOPK)
#define NPAIR   (NPAIR_R + T_TOK * ES)
#define EPSR    1.1920929e-07f

// ---------------- GEMM tile config (round-7 optimum) ----------------
#define BMG   256                 // block M
#define BNG   128                 // block N
#define BK    64                  // block K
#define AST   36                  // uint32 stride per A row (32 data + 4 pad)
#define BST   68                  // uint32 stride per B k-row (64 data + 4 pad)
#define ABUF_BYTES (BMG * AST * 4)  // 36864
#define BBUF_BYTES (BK * BST * 4)   // 17408
#define BBUFW (BK * BST)
#define BOFF  (2 * ABUF_BYTES)      // 73728
#define XOFF  (BOFF + 2 * BBUF_BYTES) // 108544
#define DSMEM (XOFF + 2048)         // 110592 bytes dynamic smem

// ---------------- device scratch ----------------
__device__ float    g_xn [T_TOK * DM];
__device__ uint32_t g_xnb[T_TOK * DM / 2];
__device__ int      g_idx[T_TOK * TOPK];
__device__ float    g_wk [T_TOK * TOPK];
__device__ int      g_cnt[NGRP];
__device__ int      g_off[NGRP + 1];
__device__ int      g_fill[ER];
__device__ int      g_ptok[NPAIR];
__device__ float    g_pw  [NPAIR];
__device__ int      g_pos [T_TOK * 8];
__device__ uint32_t g_hb  [(size_t)NPAIR * HM / 2];
__device__ uint32_t g_gb  [(size_t)NPAIR * HM / 2];
__device__ float    g_po  [(size_t)NPAIR * DM];

// ---------------- PTX helpers ----------------
__device__ __forceinline__ uint32_t pk(float lo, float hi) {
    uint32_t r;
    asm("cvt.rn.bf16x2.f32 %0, %1, %2;" : "=r"(r) : "f"(hi), "f"(lo));
    return r;
}
__device__ __forceinline__ uint32_t cvta(const void* p) {
    return (uint32_t)__cvta_generic_to_shared(p);
}
__device__ __forceinline__ void mma_bf16(float* c, uint32_t a0, uint32_t a1,
                                         uint32_t a2, uint32_t a3,
                                         uint32_t b0, uint32_t b1) {
    asm volatile(
        "mma.sync.aligned.m16n8k16.row.col.f32.bf16.bf16.f32 "
        "{%0,%1,%2,%3}, {%4,%5,%6,%7}, {%8,%9}, {%0,%1,%2,%3};\n"
        : "+f"(c[0]), "+f"(c[1]), "+f"(c[2]), "+f"(c[3])
        : "r"(a0), "r"(a1), "r"(a2), "r"(a3), "r"(b0), "r"(b1));
}
__device__ __forceinline__ void ldsm4(uint32_t& r0, uint32_t& r1, uint32_t& r2,
                                      uint32_t& r3, uint32_t a) {
    asm volatile("ldmatrix.sync.aligned.m8n8.x4.shared.b16 {%0,%1,%2,%3}, [%4];"
                 : "=r"(r0), "=r"(r1), "=r"(r2), "=r"(r3) : "r"(a));
}
__device__ __forceinline__ void ldsm4t(uint32_t& r0, uint32_t& r1, uint32_t& r2,
                                       uint32_t& r3, uint32_t a) {
    asm volatile("ldmatrix.sync.aligned.m8n8.x4.trans.shared.b16 {%0,%1,%2,%3}, [%4];"
                 : "=r"(r0), "=r"(r1), "=r"(r2), "=r"(r3) : "r"(a));
}
// .cg: bypass L1 — A gather data has no L1 reuse and L1 is the hot pipe
#define CPA(dst, src) \
    asm volatile("cp.async.cg.shared.global [%0], [%1], 16;" \
                 :: "r"(dst), "l"(src) : "memory")
#define CPC() asm volatile("cp.async.commit_group;" ::: "memory")
#define CPW() asm volatile("cp.async.wait_group 0;" ::: "memory")
#define CPA4(dstv, srcv) do { \
    uint32_t _d = (dstv); const uint32_t* _s = (srcv); \
    CPA(_d, _s); CPA(_d + 16, _s + 4); CPA(_d + 32, _s + 8); CPA(_d + 48, _s + 12); \
} while (0)

// ---------------- kernel 1: RMSNorm + residual init (+counter reset) --------
__global__ void __launch_bounds__(256) k_rmsnorm(const float* __restrict__ x,
                                                 const float* __restrict__ nw,
                                                 float* __restrict__ out) {
    int t = blockIdx.x, tid = threadIdx.x;
    if (blockIdx.x == 0) {
        if (tid < NGRP) g_cnt[tid] = (tid < ER) ? 0 : T_TOK;
        if (tid >= 128 && tid < 128 + ER) g_fill[tid - 128] = 0;
    }
    const float4* xr = (const float4*)(x + (size_t)t * DM);
    float4 a = xr[tid];
    float s = a.x * a.x + a.y * a.y + a.z * a.z + a.w * a.w;
    #pragma unroll
    for (int o = 16; o; o >>= 1) s += __shfl_xor_sync(0xffffffffu, s, o);
    __shared__ float ws[8];
    __shared__ float s_scale;
    if ((tid & 31) == 0) ws[tid >> 5] = s;
    __syncthreads();
    if (tid == 0) {
        float tot = 0.f;
        #pragma unroll
        for (int i = 0; i < 8; i++) tot += ws[i];
        s_scale = rsqrtf(tot / (float)DM + EPSR);
    }
    __syncthreads();
    float sc = s_scale;
    float4 w4 = ((const float4*)nw)[tid];
    float4 r;
    r.x = a.x * sc * w4.x; r.y = a.y * sc * w4.y;
    r.z = a.z * sc * w4.z; r.w = a.w * sc * w4.w;
    ((float4*)g_xn)[(size_t)t * 256 + tid] = r;
    ((uint2*)g_xnb)[(size_t)t * 256 + tid] = make_uint2(pk(r.x, r.y), pk(r.z, r.w));
    ((float4*)out)[(size_t)t * 256 + tid]  = a;
}

// ---------------- kernel 2: router (raw affinities fp32 + top-6 fused) ------
#define RPAD 68
__global__ void __launch_bounds__(256) k_route(const float* __restrict__ Wr,
                                               const float* __restrict__ bias) {
    __shared__ float As[16][RPAD];
    __shared__ float Bs[16][RPAD];
    __shared__ float sraw[64][65];
    int t0 = blockIdx.x * 64;
    int tid = threadIdx.x, tx = tid & 15, ty = tid >> 4;
    float acc[4][4];
    #pragma unroll
    for (int i = 0; i < 4; i++)
        #pragma unroll
        for (int j = 0; j < 4; j++) acc[i][j] = 0.f;
    int m = tid >> 2, kv = tid & 3;
    for (int kk = 0; kk < DM; kk += 16) {
        float4 av = *(const float4*)(g_xn + (size_t)(t0 + m) * DM + kk + kv * 4);
        float4 bv = *(const float4*)(Wr + (size_t)m * DM + kk + kv * 4);
        As[kv * 4 + 0][m] = av.x; As[kv * 4 + 1][m] = av.y;
        As[kv * 4 + 2][m] = av.z; As[kv * 4 + 3][m] = av.w;
        Bs[kv * 4 + 0][m] = bv.x; Bs[kv * 4 + 1][m] = bv.y;
        Bs[kv * 4 + 2][m] = bv.z; Bs[kv * 4 + 3][m] = bv.w;
        __syncthreads();
        #pragma unroll
        for (int k = 0; k < 16; k++) {
            float4 a4 = *(float4*)&As[k][ty * 4];
            float4 b4 = *(float4*)&Bs[k][tx * 4];
            float aa[4] = {a4.x, a4.y, a4.z, a4.w};
            float bb[4] = {b4.x, b4.y, b4.z, b4.w};
            #pragma unroll
            for (int i = 0; i < 4; i++)
                #pragma unroll
                for (int j = 0; j < 4; j++) acc[i][j] += aa[i] * bb[j];
        }
        __syncthreads();
    }
    #pragma unroll
    for (int i = 0; i < 4; i++)
        #pragma unroll
        for (int j = 0; j < 4; j++)
            sraw[ty * 4 + i][tx * 4 + j] = acc[i][j];
    __syncthreads();
    int lane = tid & 31, wid = tid >> 5;
    float b0 = bias[lane], b1 = bias[lane + 32];
    #pragma unroll
    for (int q = 0; q < 8; q++) {
        int lt = wid * 8 + q;
        int t = t0 + lt;
        float r0 = sraw[lt][lane];
        float r1 = sraw[lt][lane + 32];
        float a0 = r0 + b0;
        float a1 = r1 + b1;
        float sum = 0.f;
        int   sel_e[TOPK];
        float sel_r[TOPK];
        #pragma unroll
        for (int k = 0; k < TOPK; k++) {
            float v; int e;
            if (a0 >= a1) { v = a0; e = lane; } else { v = a1; e = lane + 32; }
            #pragma unroll
            for (int o = 16; o; o >>= 1) {
                float ov = __shfl_xor_sync(0xffffffffu, v, o);
                int   oe = __shfl_xor_sync(0xffffffffu, e, o);
                if (ov > v || (ov == v && oe < e)) { v = ov; e = oe; }
            }
            if (e == lane)      a0 = -1e30f;
            if (e == lane + 32) a1 = -1e30f;
            float ra = __shfl_sync(0xffffffffu, r0, e & 31);
            float rb = __shfl_sync(0xffffffffu, r1, e & 31);
            float rs = (e < 32) ? ra : rb;
            sel_e[k] = e; sel_r[k] = rs; sum += rs;
        }
        float inv = 1.f / sum;
        if (lane < TOPK) {
            g_idx[t * TOPK + lane] = sel_e[lane];
            g_wk [t * TOPK + lane] = sel_r[lane] * inv;
            atomicAdd(&g_cnt[sel_e[lane]], 1);
        }
    }
}

// ---------------- kernel 3: scatter (fused per-block scan) ----------------
__global__ void __launch_bounds__(256) k_scatter() {
    __shared__ int s_off[NGRP + 1];
    int tid = threadIdx.x;
    if (tid == 0) {
        int acc = 0;
        #pragma unroll
        for (int i = 0; i < NGRP; i++) { s_off[i] = acc; acc += g_cnt[i]; }
        s_off[NGRP] = acc;
    }
    __syncthreads();
    if (blockIdx.x == 0 && tid <= NGRP) g_off[tid] = s_off[tid];
    int p = blockIdx.x * 256 + tid;
    if (p >= NPAIR) return;
    if (p < NPAIR_R) {
        int t = p / TOPK, k = p % TOPK;
        int e = g_idx[p];
        int pos = s_off[e] + atomicAdd(&g_fill[e], 1);
        g_ptok[pos] = t;
        g_pw  [pos] = g_wk[p];
        g_pos[t * 8 + k] = pos;
    } else {
        int q = p - NPAIR_R;
        int j = q / T_TOK, t = q % T_TOK;
        int pos = s_off[ER + j] + t;
        g_ptok[pos] = t;
        g_pw  [pos] = 1.0f;
        g_pos[t * 8 + TOPK + j] = pos;
    }
}

// ================= GEMM core (round-7): BM=256, BN=128, BK=64, 512 thr =====
// 16 warps as 8m x 2n, warp tile 32x64 (2 m16 x 8 n8)
__device__ __forceinline__ void mma_chunk(uint32_t aA, uint32_t aB,
                                          float acc[2][8][4],
                                          int warp_m, int warp_n, int lane) {
    int sel = lane >> 3, li = lane & 7;
    int arow = (sel & 1) * 8 + li;
    int acol = (sel >> 1) * 4;
    int brow = (sel & 1) * 8 + li;
    int bn   = (sel >> 1) * 8;
    #pragma unroll
    for (int ks = 0; ks < 4; ks++) {
        uint32_t a[2][4];
        #pragma unroll
        for (int s = 0; s < 2; s++) {
            uint32_t addr = aA + (uint32_t)(((warp_m * 32 + s * 16 + arow) * AST
                                             + ks * 8 + acol) * 4);
            ldsm4(a[s][0], a[s][1], a[s][2], a[s][3], addr);
        }
        #pragma unroll
        for (int p = 0; p < 4; p++) {
            uint32_t b0, b1, b2, b3;
            uint32_t addr = aB + (uint32_t)((ks * 16 + brow) * (BST * 4)
                                            + (warp_n * 64 + p * 16 + bn) * 2);
            ldsm4t(b0, b1, b2, b3, addr);
            #pragma unroll
            for (int s = 0; s < 2; s++) {
                mma_bf16(acc[s][2 * p],     a[s][0], a[s][1], a[s][2], a[s][3], b0, b1);
                mma_bf16(acc[s][2 * p + 1], a[s][0], a[s][1], a[s][2], a[s][3], b2, b3);
            }
        }
    }
}

// B chunk: 64 k-rows x 128 n fp32 -> 16 regs (512 threads)
__device__ __forceinline__ void ldB(const float* __restrict__ W, int ldb, int kk,
                                    int nb, int tid, float4 f[4]) {
    const float* p = W + (size_t)(kk + (tid >> 3)) * ldb + nb + (tid & 7) * 16;
    f[0] = *(const float4*)p;
    f[1] = *(const float4*)(p + 4);
    f[2] = *(const float4*)(p + 8);
    f[3] = *(const float4*)(p + 12);
}
__device__ __forceinline__ void stB(uint32_t* Bbase, int tid, const float4 f[4]) {
    uint32_t* d = Bbase + (tid >> 3) * BST + (tid & 7) * 8;
    *(uint4*)d = make_uint4(pk(f[0].x, f[0].y), pk(f[0].z, f[0].w),
                            pk(f[1].x, f[1].y), pk(f[1].z, f[1].w));
    *(uint4*)(d + 4) = make_uint4(pk(f[2].x, f[2].y), pk(f[2].z, f[2].w),
                                  pk(f[3].x, f[3].y), pk(f[3].z, f[3].w));
}

// ---------------- kernel 4: grouped GEMM1 h = gather(xnb) @ W1[e] + b1 ------
__global__ void __launch_bounds__(512, 1)
k_gemm1(const float* __restrict__ rW1, const float* __restrict__ sW1,
        const float* __restrict__ rb1, const float* __restrict__ sb1) {
    extern __shared__ uint8_t dyn[];
    uint32_t* Bb = (uint32_t*)(dyn + BOFF);
    const uint32_t** sArow = (const uint32_t**)(dyn + XOFF);
    uint32_t saA = cvta(dyn), saB = cvta(Bb);
    int grp = blockIdx.z;
    int start = g_off[grp], cnt = g_off[grp + 1] - start;
    if ((int)blockIdx.x * BMG >= cnt) return;
    const float* W  = (grp < ER) ? rW1 + (size_t)grp * DM * HM
                                 : sW1 + (size_t)(grp - ER) * DM * HM;
    const float* bv = (grp < ER) ? rb1 + (size_t)grp * HM
                                 : sb1 + (size_t)(grp - ER) * HM;
    int nb = blockIdx.y * BNG;
    int tid = threadIdx.x, lane = tid & 31, wid = tid >> 5;
    int warp_m = wid >> 1, warp_n = wid & 1;
    int amf = tid >> 1, ahalf = (tid & 1) * 16;

    for (int mt = blockIdx.x; mt * BMG < cnt; mt += gridDim.x) {
        int m0 = mt * BMG;
        int rem = cnt - m0; if (rem > BMG) rem = BMG;
        bool active = (warp_m * 32 < rem);
        __syncthreads();
        if (tid < BMG)
            sArow[tid] = (tid < rem)
                ? g_xnb + (size_t)g_ptok[start + m0 + tid] * (DM / 2) : g_xnb;
        __syncthreads();
        float acc[2][8][4];
        #pragma unroll
        for (int s = 0; s < 2; s++)
            #pragma unroll
            for (int n = 0; n < 8; n++)
                #pragma unroll
                for (int j = 0; j < 4; j++) acc[s][n][j] = 0.f;
        {
            float4 f[4];
            ldB(W, HM, 0, nb, tid, f);
            stB(Bb, tid, f);
            CPA4(saA + (uint32_t)((amf * AST + ahalf) * 4), sArow[amf] + ahalf);
            CPC(); CPW();
        }
        __syncthreads();
        int buf = 0;
        for (int c = 0; c < DM / BK; c++) {
            float4 f[4];
            bool pre = (c + 1 < DM / BK);
            if (pre) {
                ldB(W, HM, (c + 1) * BK, nb, tid, f);
                CPA4(saA + (buf ^ 1) * ABUF_BYTES + (uint32_t)((amf * AST + ahalf) * 4),
                     sArow[amf] + (c + 1) * 32 + ahalf);
                CPC();
            }
            if (active)
                mma_chunk(saA + buf * ABUF_BYTES, saB + buf * BBUF_BYTES,
                          acc, warp_m, warp_n, lane);
            if (pre) stB(Bb + (buf ^ 1) * BBUFW, tid, f);
            CPW();
            __syncthreads();
            buf ^= 1;
        }
        if (active) {
            #pragma unroll
            for (int s = 0; s < 2; s++) {
                int mrow = warp_m * 32 + s * 16 + (lane >> 2);
                #pragma unroll
                for (int nt = 0; nt < 8; nt++) {
                    int col = nb + warp_n * 64 + nt * 8 + (lane & 3) * 2;
                    float2 bb = *(const float2*)&bv[col];
                    if (mrow < rem) {
                        size_t p = (size_t)(start + m0 + mrow);
                        g_hb[(p * HM + col) >> 1] =
                            pk(acc[s][nt][0] + bb.x, acc[s][nt][1] + bb.y);
                    }
                    if (mrow + 8 < rem) {
                        size_t p = (size_t)(start + m0 + mrow + 8);
                        g_hb[(p * HM + col) >> 1] =
                            pk(acc[s][nt][2] + bb.x, acc[s][nt][3] + bb.y);
                    }
                }
            }
        }
    }
}

// ---------------- kernel 5: gate  g = silu(h @ Wg) * h ----------------
__global__ void __launch_bounds__(512, 1)
k_gate(const float* __restrict__ rWg, const float* __restrict__ sWg) {
    extern __shared__ uint8_t dyn[];
    uint32_t* Bb = (uint32_t*)(dyn + BOFF);
    uint32_t saA = cvta(dyn), saB = cvta(Bb);
    int p0 = blockIdx.x * BMG;
    const float* W = (p0 < NPAIR_R) ? rWg : sWg;
    int nb = blockIdx.y * BNG;
    int tid = threadIdx.x, lane = tid & 31, wid = tid >> 5;
    int warp_m = wid >> 1, warp_n = wid & 1;
    int amf = tid >> 1, ahalf = (tid & 1) * 16;
    const uint32_t* arow = g_hb + (size_t)(p0 + amf) * (HM / 2);

    float acc[2][8][4];
    #pragma unroll
    for (int s = 0; s < 2; s++)
        #pragma unroll
        for (int n = 0; n < 8; n++)
            #pragma unroll
            for (int j = 0; j < 4; j++) acc[s][n][j] = 0.f;
    {
        float4 f[4];
        ldB(W, HM, 0, nb, tid, f);
        stB(Bb, tid, f);
        CPA4(saA + (uint32_t)((amf * AST + ahalf) * 4), arow + ahalf);
        CPC(); CPW();
    }
    __syncthreads();
    int buf = 0;
    for (int c = 0; c < HM / BK; c++) {
        float4 f[4];
        bool pre = (c + 1 < HM / BK);
        if (pre) {
            ldB(W, HM, (c + 1) * BK, nb, tid, f);
            CPA4(saA + (buf ^ 1) * ABUF_BYTES + (uint32_t)((amf * AST + ahalf) * 4),
                 arow + (c + 1) * 32 + ahalf);
            CPC();
        }
        mma_chunk(saA + buf * ABUF_BYTES, saB + buf * BBUF_BYTES,
                  acc, warp_m, warp_n, lane);
        if (pre) stB(Bb + (buf ^ 1) * BBUFW, tid, f);
        CPW();
        __syncthreads();
        buf ^= 1;
    }
    #pragma unroll
    for (int s = 0; s < 2; s++) {
        int mrow = warp_m * 32 + s * 16 + (lane >> 2);
        #pragma unroll
        for (int nt = 0; nt < 8; nt++) {
            int col = nb + warp_n * 64 + nt * 8 + (lane & 3) * 2;
            #pragma unroll
            for (int hh = 0; hh < 2; hh++) {
                size_t p = (size_t)(p0 + mrow + hh * 8);
                size_t idx = (p * HM + col) >> 1;
                uint32_t hu = g_hb[idx];
                float h0 = __uint_as_float(hu << 16);
                float h1 = __uint_as_float(hu & 0xffff0000u);
                float v0 = acc[s][nt][hh * 2 + 0];
                float v1 = acc[s][nt][hh * 2 + 1];
                float r0 = (v0 / (1.f + __expf(-v0))) * h0;
                float r1 = (v1 / (1.f + __expf(-v1))) * h1;
                g_gb[idx] = pk(r0, r1);
            }
        }
    }
}

// ---------------- kernel 6: grouped GEMM2 po = (g @ W2[e] + b2) * w ----------
__global__ void __launch_bounds__(512, 1)
k_gemm2(const float* __restrict__ rW2, const float* __restrict__ sW2,
        const float* __restrict__ rb2, const float* __restrict__ sb2) {
    extern __shared__ uint8_t dyn[];
    uint32_t* Bb = (uint32_t*)(dyn + BOFF);
    float* sPw = (float*)(dyn + XOFF);
    uint32_t saA = cvta(dyn), saB = cvta(Bb);
    int grp = blockIdx.z;
    int start = g_off[grp], cnt = g_off[grp + 1] - start;
    if ((int)blockIdx.x * BMG >= cnt) return;
    const float* W  = (grp < ER) ? rW2 + (size_t)grp * HM * DM
                                 : sW2 + (size_t)(grp - ER) * HM * DM;
    const float* bv = (grp < ER) ? rb2 + (size_t)grp * DM
                                 : sb2 + (size_t)(grp - ER) * DM;
    int nb = blockIdx.y * BNG;
    int tid = threadIdx.x, lane = tid & 31, wid = tid >> 5;
    int warp_m = wid >> 1, warp_n = wid & 1;
    int amf = tid >> 1, ahalf = (tid & 1) * 16;

    for (int mt = blockIdx.x; mt * BMG < cnt; mt += gridDim.x) {
        int m0 = mt * BMG;
        int rem = cnt - m0; if (rem > BMG) rem = BMG;
        bool active = (warp_m * 32 < rem);
        __syncthreads();
        if (tid < BMG) sPw[tid] = (tid < rem) ? g_pw[start + m0 + tid] : 0.f;
        __syncthreads();
        int ar = amf < rem ? amf : (rem - 1);
        const uint32_t* arow = g_gb + (size_t)(start + m0 + ar) * (HM / 2);
        float acc[2][8][4];
        #pragma unroll
        for (int s = 0; s < 2; s++)
            #pragma unroll
            for (int n = 0; n < 8; n++)
                #pragma unroll
                for (int j = 0; j < 4; j++) acc[s][n][j] = 0.f;
        {
            float4 f[4];
            ldB(W, DM, 0, nb, tid, f);
            stB(Bb, tid, f);
            CPA4(saA + (uint32_t)((amf * AST + ahalf) * 4), arow + ahalf);
            CPC(); CPW();
        }
        __syncthreads();
        int buf = 0;
        for (int c = 0; c < HM / BK; c++) {
            float4 f[4];
            bool pre = (c + 1 < HM / BK);
            if (pre) {
                ldB(W, DM, (c + 1) * BK, nb, tid, f);
                CPA4(saA + (buf ^ 1) * ABUF_BYTES + (uint32_t)((amf * AST + ahalf) * 4),
                     arow + (c + 1) * 32 + ahalf);
                CPC();
            }
            if (active)
                mma_chunk(saA + buf * ABUF_BYTES, saB + buf * BBUF_BYTES,
                          acc, warp_m, warp_n, lane);
            if (pre) stB(Bb + (buf ^ 1) * BBUFW, tid, f);
            CPW();
            __syncthreads();
            buf ^= 1;
        }
        if (active) {
            #pragma unroll
            for (int s = 0; s < 2; s++) {
                int mrow = warp_m * 32 + s * 16 + (lane >> 2);
                #pragma unroll
                for (int nt = 0; nt < 8; nt++) {
                    int col = nb + warp_n * 64 + nt * 8 + (lane & 3) * 2;
                    float2 bb = *(const float2*)&bv[col];
                    if (mrow < rem) {
                        size_t p = (size_t)(start + m0 + mrow);
                        float w = sPw[mrow];
                        *(float2*)&g_po[p * DM + col] =
                            make_float2((acc[s][nt][0] + bb.x) * w,
                                        (acc[s][nt][1] + bb.y) * w);
                    }
                    if (mrow + 8 < rem) {
                        size_t p = (size_t)(start + m0 + mrow + 8);
                        float w = sPw[mrow + 8];
                        *(float2*)&g_po[p * DM + col] =
                            make_float2((acc[s][nt][2] + bb.x) * w,
                                        (acc[s][nt][3] + bb.y) * w);
                    }
                }
            }
        }
    }
}

// ---------------- kernel 7: per-token reduce of 8 pair rows ----------------
__global__ void __launch_bounds__(256) k_reduce(float* __restrict__ out) {
    int t = blockIdx.x, tid = threadIdx.x;
    __shared__ int pos[8];
    if (tid < 8) pos[tid] = g_pos[t * 8 + tid];
    __syncthreads();
    size_t d0 = (size_t)tid * 4;
    float4 s = *(float4*)&out[(size_t)t * DM + d0];
    #pragma unroll
    for (int j = 0; j < 8; j++) {
        float4 v = *(const float4*)&g_po[(size_t)pos[j] * DM + d0];
        s.x += v.x; s.y += v.y; s.z += v.z; s.w += v.w;
    }
    *(float4*)&out[(size_t)t * DM + d0] = s;
}

// ---------------- launcher ----------------
extern "C" void kernel_launch(void* const* d_in, const int* in_sizes, int n_in,
                              void* d_out, int out_size) {
    const float* x      = (const float*)d_in[0];
    const float* norm_w = (const float*)d_in[1];
    const float* Wr     = (const float*)d_in[2];
    const float* sW1    = (const float*)d_in[3];
    const float* sb1    = (const float*)d_in[4];
    const float* sW2    = (const float*)d_in[5];
    const float* sb2    = (const float*)d_in[6];
    const float* sWg    = (const float*)d_in[7];
    const float* rW1    = (const float*)d_in[8];
    const float* rb1    = (const float*)d_in[9];
    const float* rW2    = (const float*)d_in[10];
    const float* rb2    = (const float*)d_in[11];
    const float* rWg    = (const float*)d_in[12];
    const float* bias   = (const float*)d_in[13];
    float* out = (float*)d_out;

    cudaFuncSetAttribute(k_gemm1, cudaFuncAttributeMaxDynamicSharedMemorySize, DSMEM);
    cudaFuncSetAttribute(k_gate,  cudaFuncAttributeMaxDynamicSharedMemorySize, DSMEM);
    cudaFuncSetAttribute(k_gemm2, cudaFuncAttributeMaxDynamicSharedMemorySize, DSMEM);

    k_rmsnorm<<<T_TOK, 256>>>(x, norm_w, out);
    k_route<<<T_TOK / 64, 256>>>(Wr, bias);
    k_scatter<<<(NPAIR + 255) / 256, 256>>>();
    k_gemm1<<<dim3(8, HM / BNG, NGRP), 512, DSMEM>>>(rW1, sW1, rb1, sb1);
    k_gate<<<dim3(NPAIR / BMG, HM / BNG), 512, DSMEM>>>(rWg, sWg);
    k_gemm2<<<dim3(8, DM / BNG, NGRP), 512, DSMEM>>>(rW2, sW2, rb2, sb2);
    k_reduce<<<T_TOK, 256>>>(out);
}

// round 11
// speedup vs baseline: 1.2590x; 1.2590x over previous
#include <cuda_runtime.h>
#include <math.h>
#include <stdint.h>

// ---------------- problem constants ----------------
#define T_TOK   2048
#define DM      1024
#define HM      512
#define ER      64
#define TOPK    6
#define ES      2
#define NGRP    (ER + ES)
#define NPAIR_R (T_TOK * TOPK)
#define NPAIR   (NPAIR_R + T_TOK * ES)
#define EPSR    1.1920929e-07f

// ---------------- GEMM tile config (round-7 optimum) ----------------
#define BMG   256                 // block M
#define BNG   128                 // block N
#define BK    64                  // block K
#define AST   36                  // uint32 stride per A row (32 data + 4 pad)
#define BST   68                  // uint32 stride per B k-row (64 data + 4 pad)
#define ABUF_BYTES (BMG * AST * 4)  // 36864
#define BBUF_BYTES (BK * BST * 4)   // 17408
#define BBUFW (BK * BST)
#define BOFF  (2 * ABUF_BYTES)      // 73728
#define XOFF  (BOFF + 2 * BBUF_BYTES) // 108544
#define DSMEM (XOFF + 2048)         // 110592 bytes dynamic smem

// ---------------- device scratch ----------------
__device__ float    g_xn [T_TOK * DM];
__device__ uint32_t g_xnb[T_TOK * DM / 2];
__device__ int      g_idx[T_TOK * TOPK];
__device__ float    g_wk [T_TOK * TOPK];
__device__ int      g_cnt[NGRP];
__device__ int      g_off[NGRP + 1];
__device__ int      g_fill[ER];
__device__ int      g_ptok[NPAIR];
__device__ float    g_pw  [NPAIR];
__device__ int      g_pos [T_TOK * 8];
__device__ uint32_t g_hb  [(size_t)NPAIR * HM / 2];
__device__ uint32_t g_gb  [(size_t)NPAIR * HM / 2];
__device__ float    g_po  [(size_t)NPAIR * DM];

// ---------------- PTX helpers ----------------
__device__ __forceinline__ uint32_t pk(float lo, float hi) {
    uint32_t r;
    asm("cvt.rn.bf16x2.f32 %0, %1, %2;" : "=r"(r) : "f"(hi), "f"(lo));
    return r;
}
__device__ __forceinline__ uint32_t cvta(const void* p) {
    return (uint32_t)__cvta_generic_to_shared(p);
}
__device__ __forceinline__ void mma_bf16(float* c, uint32_t a0, uint32_t a1,
                                         uint32_t a2, uint32_t a3,
                                         uint32_t b0, uint32_t b1) {
    asm volatile(
        "mma.sync.aligned.m16n8k16.row.col.f32.bf16.bf16.f32 "
        "{%0,%1,%2,%3}, {%4,%5,%6,%7}, {%8,%9}, {%0,%1,%2,%3};\n"
        : "+f"(c[0]), "+f"(c[1]), "+f"(c[2]), "+f"(c[3])
        : "r"(a0), "r"(a1), "r"(a2), "r"(a3), "r"(b0), "r"(b1));
}
__device__ __forceinline__ void ldsm4(uint32_t& r0, uint32_t& r1, uint32_t& r2,
                                      uint32_t& r3, uint32_t a) {
    asm volatile("ldmatrix.sync.aligned.m8n8.x4.shared.b16 {%0,%1,%2,%3}, [%4];"
                 : "=r"(r0), "=r"(r1), "=r"(r2), "=r"(r3) : "r"(a));
}
__device__ __forceinline__ void ldsm4t(uint32_t& r0, uint32_t& r1, uint32_t& r2,
                                       uint32_t& r3, uint32_t a) {
    asm volatile("ldmatrix.sync.aligned.m8n8.x4.trans.shared.b16 {%0,%1,%2,%3}, [%4];"
                 : "=r"(r0), "=r"(r1), "=r"(r2), "=r"(r3) : "r"(a));
}
// .ca: KEEP L1 caching — A gather rows are re-read by sibling n-tiles (round-10
// .cg experiment regressed k_gemm1 131->235us; L1 reuse is real)
#define CPA(dst, src) \
    asm volatile("cp.async.ca.shared.global [%0], [%1], 16;" \
                 :: "r"(dst), "l"(src) : "memory")
#define CPC() asm volatile("cp.async.commit_group;" ::: "memory")
#define CPW() asm volatile("cp.async.wait_group 0;" ::: "memory")
#define CPA4(dstv, srcv) do { \
    uint32_t _d = (dstv); const uint32_t* _s = (srcv); \
    CPA(_d, _s); CPA(_d + 16, _s + 4); CPA(_d + 32, _s + 8); CPA(_d + 48, _s + 12); \
} while (0)

// ---------------- kernel 1: RMSNorm + residual init (+counter reset) --------
__global__ void __launch_bounds__(256) k_rmsnorm(const float* __restrict__ x,
                                                 const float* __restrict__ nw,
                                                 float* __restrict__ out) {
    int t = blockIdx.x, tid = threadIdx.x;
    if (blockIdx.x == 0) {
        if (tid < NGRP) g_cnt[tid] = (tid < ER) ? 0 : T_TOK;
        if (tid >= 128 && tid < 128 + ER) g_fill[tid - 128] = 0;
    }
    const float4* xr = (const float4*)(x + (size_t)t * DM);
    float4 a = xr[tid];
    float s = a.x * a.x + a.y * a.y + a.z * a.z + a.w * a.w;
    #pragma unroll
    for (int o = 16; o; o >>= 1) s += __shfl_xor_sync(0xffffffffu, s, o);
    __shared__ float ws[8];
    __shared__ float s_scale;
    if ((tid & 31) == 0) ws[tid >> 5] = s;
    __syncthreads();
    if (tid == 0) {
        float tot = 0.f;
        #pragma unroll
        for (int i = 0; i < 8; i++) tot += ws[i];
        s_scale = rsqrtf(tot / (float)DM + EPSR);
    }
    __syncthreads();
    float sc = s_scale;
    float4 w4 = ((const float4*)nw)[tid];
    float4 r;
    r.x = a.x * sc * w4.x; r.y = a.y * sc * w4.y;
    r.z = a.z * sc * w4.z; r.w = a.w * sc * w4.w;
    ((float4*)g_xn)[(size_t)t * 256 + tid] = r;
    ((uint2*)g_xnb)[(size_t)t * 256 + tid] = make_uint2(pk(r.x, r.y), pk(r.z, r.w));
    ((float4*)out)[(size_t)t * 256 + tid]  = a;
}

// ---------------- kernel 2: router (raw affinities fp32 + top-6 fused) ------
#define RPAD 68
__global__ void __launch_bounds__(256) k_route(const float* __restrict__ Wr,
                                               const float* __restrict__ bias) {
    __shared__ float As[16][RPAD];
    __shared__ float Bs[16][RPAD];
    __shared__ float sraw[64][65];
    int t0 = blockIdx.x * 64;
    int tid = threadIdx.x, tx = tid & 15, ty = tid >> 4;
    float acc[4][4];
    #pragma unroll
    for (int i = 0; i < 4; i++)
        #pragma unroll
        for (int j = 0; j < 4; j++) acc[i][j] = 0.f;
    int m = tid >> 2, kv = tid & 3;
    for (int kk = 0; kk < DM; kk += 16) {
        float4 av = *(const float4*)(g_xn + (size_t)(t0 + m) * DM + kk + kv * 4);
        float4 bv = *(const float4*)(Wr + (size_t)m * DM + kk + kv * 4);
        As[kv * 4 + 0][m] = av.x; As[kv * 4 + 1][m] = av.y;
        As[kv * 4 + 2][m] = av.z; As[kv * 4 + 3][m] = av.w;
        Bs[kv * 4 + 0][m] = bv.x; Bs[kv * 4 + 1][m] = bv.y;
        Bs[kv * 4 + 2][m] = bv.z; Bs[kv * 4 + 3][m] = bv.w;
        __syncthreads();
        #pragma unroll
        for (int k = 0; k < 16; k++) {
            float4 a4 = *(float4*)&As[k][ty * 4];
            float4 b4 = *(float4*)&Bs[k][tx * 4];
            float aa[4] = {a4.x, a4.y, a4.z, a4.w};
            float bb[4] = {b4.x, b4.y, b4.z, b4.w};
            #pragma unroll
            for (int i = 0; i < 4; i++)
                #pragma unroll
                for (int j = 0; j < 4; j++) acc[i][j] += aa[i] * bb[j];
        }
        __syncthreads();
    }
    #pragma unroll
    for (int i = 0; i < 4; i++)
        #pragma unroll
        for (int j = 0; j < 4; j++)
            sraw[ty * 4 + i][tx * 4 + j] = acc[i][j];
    __syncthreads();
    int lane = tid & 31, wid = tid >> 5;
    float b0 = bias[lane], b1 = bias[lane + 32];
    #pragma unroll
    for (int q = 0; q < 8; q++) {
        int lt = wid * 8 + q;
        int t = t0 + lt;
        float r0 = sraw[lt][lane];
        float r1 = sraw[lt][lane + 32];
        float a0 = r0 + b0;
        float a1 = r1 + b1;
        float sum = 0.f;
        int   sel_e[TOPK];
        float sel_r[TOPK];
        #pragma unroll
        for (int k = 0; k < TOPK; k++) {
            float v; int e;
            if (a0 >= a1) { v = a0; e = lane; } else { v = a1; e = lane + 32; }
            #pragma unroll
            for (int o = 16; o; o >>= 1) {
                float ov = __shfl_xor_sync(0xffffffffu, v, o);
                int   oe = __shfl_xor_sync(0xffffffffu, e, o);
                if (ov > v || (ov == v && oe < e)) { v = ov; e = oe; }
            }
            if (e == lane)      a0 = -1e30f;
            if (e == lane + 32) a1 = -1e30f;
            float ra = __shfl_sync(0xffffffffu, r0, e & 31);
            float rb = __shfl_sync(0xffffffffu, r1, e & 31);
            float rs = (e < 32) ? ra : rb;
            sel_e[k] = e; sel_r[k] = rs; sum += rs;
        }
        float inv = 1.f / sum;
        if (lane < TOPK) {
            g_idx[t * TOPK + lane] = sel_e[lane];
            g_wk [t * TOPK + lane] = sel_r[lane] * inv;
            atomicAdd(&g_cnt[sel_e[lane]], 1);
        }
    }
}

// ---------------- kernel 3: scatter (fused per-block scan) ----------------
__global__ void __launch_bounds__(256) k_scatter() {
    __shared__ int s_off[NGRP + 1];
    int tid = threadIdx.x;
    if (tid == 0) {
        int acc = 0;
        #pragma unroll
        for (int i = 0; i < NGRP; i++) { s_off[i] = acc; acc += g_cnt[i]; }
        s_off[NGRP] = acc;
    }
    __syncthreads();
    if (blockIdx.x == 0 && tid <= NGRP) g_off[tid] = s_off[tid];
    int p = blockIdx.x * 256 + tid;
    if (p >= NPAIR) return;
    if (p < NPAIR_R) {
        int t = p / TOPK, k = p % TOPK;
        int e = g_idx[p];
        int pos = s_off[e] + atomicAdd(&g_fill[e], 1);
        g_ptok[pos] = t;
        g_pw  [pos] = g_wk[p];
        g_pos[t * 8 + k] = pos;
    } else {
        int q = p - NPAIR_R;
        int j = q / T_TOK, t = q % T_TOK;
        int pos = s_off[ER + j] + t;
        g_ptok[pos] = t;
        g_pw  [pos] = 1.0f;
        g_pos[t * 8 + TOPK + j] = pos;
    }
}

// ================= GEMM core (round-7): BM=256, BN=128, BK=64, 512 thr =====
// 16 warps as 8m x 2n, warp tile 32x64 (2 m16 x 8 n8)
__device__ __forceinline__ void mma_chunk(uint32_t aA, uint32_t aB,
                                          float acc[2][8][4],
                                          int warp_m, int warp_n, int lane) {
    int sel = lane >> 3, li = lane & 7;
    int arow = (sel & 1) * 8 + li;
    int acol = (sel >> 1) * 4;
    int brow = (sel & 1) * 8 + li;
    int bn   = (sel >> 1) * 8;
    #pragma unroll
    for (int ks = 0; ks < 4; ks++) {
        uint32_t a[2][4];
        #pragma unroll
        for (int s = 0; s < 2; s++) {
            uint32_t addr = aA + (uint32_t)(((warp_m * 32 + s * 16 + arow) * AST
                                             + ks * 8 + acol) * 4);
            ldsm4(a[s][0], a[s][1], a[s][2], a[s][3], addr);
        }
        #pragma unroll
        for (int p = 0; p < 4; p++) {
            uint32_t b0, b1, b2, b3;
            uint32_t addr = aB + (uint32_t)((ks * 16 + brow) * (BST * 4)
                                            + (warp_n * 64 + p * 16 + bn) * 2);
            ldsm4t(b0, b1, b2, b3, addr);
            #pragma unroll
            for (int s = 0; s < 2; s++) {
                mma_bf16(acc[s][2 * p],     a[s][0], a[s][1], a[s][2], a[s][3], b0, b1);
                mma_bf16(acc[s][2 * p + 1], a[s][0], a[s][1], a[s][2], a[s][3], b2, b3);
            }
        }
    }
}

// B chunk: 64 k-rows x 128 n fp32 -> 16 regs (512 threads)
__device__ __forceinline__ void ldB(const float* __restrict__ W, int ldb, int kk,
                                    int nb, int tid, float4 f[4]) {
    const float* p = W + (size_t)(kk + (tid >> 3)) * ldb + nb + (tid & 7) * 16;
    f[0] = *(const float4*)p;
    f[1] = *(const float4*)(p + 4);
    f[2] = *(const float4*)(p + 8);
    f[3] = *(const float4*)(p + 12);
}
__device__ __forceinline__ void stB(uint32_t* Bbase, int tid, const float4 f[4]) {
    uint32_t* d = Bbase + (tid >> 3) * BST + (tid & 7) * 8;
    *(uint4*)d = make_uint4(pk(f[0].x, f[0].y), pk(f[0].z, f[0].w),
                            pk(f[1].x, f[1].y), pk(f[1].z, f[1].w));
    *(uint4*)(d + 4) = make_uint4(pk(f[2].x, f[2].y), pk(f[2].z, f[2].w),
                                  pk(f[3].x, f[3].y), pk(f[3].z, f[3].w));
}

// ---------------- kernel 4: grouped GEMM1 h = gather(xnb) @ W1[e] + b1 ------
__global__ void __launch_bounds__(512, 1)
k_gemm1(const float* __restrict__ rW1, const float* __restrict__ sW1,
        const float* __restrict__ rb1, const float* __restrict__ sb1) {
    extern __shared__ uint8_t dyn[];
    uint32_t* Bb = (uint32_t*)(dyn + BOFF);
    const uint32_t** sArow = (const uint32_t**)(dyn + XOFF);
    uint32_t saA = cvta(dyn), saB = cvta(Bb);
    int grp = blockIdx.z;
    int start = g_off[grp], cnt = g_off[grp + 1] - start;
    if ((int)blockIdx.x * BMG >= cnt) return;
    const float* W  = (grp < ER) ? rW1 + (size_t)grp * DM * HM
                                 : sW1 + (size_t)(grp - ER) * DM * HM;
    const float* bv = (grp < ER) ? rb1 + (size_t)grp * HM
                                 : sb1 + (size_t)(grp - ER) * HM;
    int nb = blockIdx.y * BNG;
    int tid = threadIdx.x, lane = tid & 31, wid = tid >> 5;
    int warp_m = wid >> 1, warp_n = wid & 1;
    int amf = tid >> 1, ahalf = (tid & 1) * 16;

    for (int mt = blockIdx.x; mt * BMG < cnt; mt += gridDim.x) {
        int m0 = mt * BMG;
        int rem = cnt - m0; if (rem > BMG) rem = BMG;
        bool active = (warp_m * 32 < rem);
        __syncthreads();
        if (tid < BMG)
            sArow[tid] = (tid < rem)
                ? g_xnb + (size_t)g_ptok[start + m0 + tid] * (DM / 2) : g_xnb;
        __syncthreads();
        float acc[2][8][4];
        #pragma unroll
        for (int s = 0; s < 2; s++)
            #pragma unroll
            for (int n = 0; n < 8; n++)
                #pragma unroll
                for (int j = 0; j < 4; j++) acc[s][n][j] = 0.f;
        {
            float4 f[4];
            ldB(W, HM, 0, nb, tid, f);
            stB(Bb, tid, f);
            CPA4(saA + (uint32_t)((amf * AST + ahalf) * 4), sArow[amf] + ahalf);
            CPC(); CPW();
        }
        __syncthreads();
        int buf = 0;
        for (int c = 0; c < DM / BK; c++) {
            float4 f[4];
            bool pre = (c + 1 < DM / BK);
            if (pre) {
                ldB(W, HM, (c + 1) * BK, nb, tid, f);
                CPA4(saA + (buf ^ 1) * ABUF_BYTES + (uint32_t)((amf * AST + ahalf) * 4),
                     sArow[amf] + (c + 1) * 32 + ahalf);
                CPC();
            }
            if (active)
                mma_chunk(saA + buf * ABUF_BYTES, saB + buf * BBUF_BYTES,
                          acc, warp_m, warp_n, lane);
            if (pre) stB(Bb + (buf ^ 1) * BBUFW, tid, f);
            CPW();
            __syncthreads();
            buf ^= 1;
        }
        if (active) {
            #pragma unroll
            for (int s = 0; s < 2; s++) {
                int mrow = warp_m * 32 + s * 16 + (lane >> 2);
                #pragma unroll
                for (int nt = 0; nt < 8; nt++) {
                    int col = nb + warp_n * 64 + nt * 8 + (lane & 3) * 2;
                    float2 bb = *(const float2*)&bv[col];
                    if (mrow < rem) {
                        size_t p = (size_t)(start + m0 + mrow);
                        g_hb[(p * HM + col) >> 1] =
                            pk(acc[s][nt][0] + bb.x, acc[s][nt][1] + bb.y);
                    }
                    if (mrow + 8 < rem) {
                        size_t p = (size_t)(start + m0 + mrow + 8);
                        g_hb[(p * HM + col) >> 1] =
                            pk(acc[s][nt][2] + bb.x, acc[s][nt][3] + bb.y);
                    }
                }
            }
        }
    }
}

// ---------------- kernel 5: gate  g = silu(h @ Wg) * h ----------------
__global__ void __launch_bounds__(512, 1)
k_gate(const float* __restrict__ rWg, const float* __restrict__ sWg) {
    extern __shared__ uint8_t dyn[];
    uint32_t* Bb = (uint32_t*)(dyn + BOFF);
    uint32_t saA = cvta(dyn), saB = cvta(Bb);
    int p0 = blockIdx.x * BMG;
    const float* W = (p0 < NPAIR_R) ? rWg : sWg;
    int nb = blockIdx.y * BNG;
    int tid = threadIdx.x, lane = tid & 31, wid = tid >> 5;
    int warp_m = wid >> 1, warp_n = wid & 1;
    int amf = tid >> 1, ahalf = (tid & 1) * 16;
    const uint32_t* arow = g_hb + (size_t)(p0 + amf) * (HM / 2);

    float acc[2][8][4];
    #pragma unroll
    for (int s = 0; s < 2; s++)
        #pragma unroll
        for (int n = 0; n < 8; n++)
            #pragma unroll
            for (int j = 0; j < 4; j++) acc[s][n][j] = 0.f;
    {
        float4 f[4];
        ldB(W, HM, 0, nb, tid, f);
        stB(Bb, tid, f);
        CPA4(saA + (uint32_t)((amf * AST + ahalf) * 4), arow + ahalf);
        CPC(); CPW();
    }
    __syncthreads();
    int buf = 0;
    for (int c = 0; c < HM / BK; c++) {
        float4 f[4];
        bool pre = (c + 1 < HM / BK);
        if (pre) {
            ldB(W, HM, (c + 1) * BK, nb, tid, f);
            CPA4(saA + (buf ^ 1) * ABUF_BYTES + (uint32_t)((amf * AST + ahalf) * 4),
                 arow + (c + 1) * 32 + ahalf);
            CPC();
        }
        mma_chunk(saA + buf * ABUF_BYTES, saB + buf * BBUF_BYTES,
                  acc, warp_m, warp_n, lane);
        if (pre) stB(Bb + (buf ^ 1) * BBUFW, tid, f);
        CPW();
        __syncthreads();
        buf ^= 1;
    }
    #pragma unroll
    for (int s = 0; s < 2; s++) {
        int mrow = warp_m * 32 + s * 16 + (lane >> 2);
        #pragma unroll
        for (int nt = 0; nt < 8; nt++) {
            int col = nb + warp_n * 64 + nt * 8 + (lane & 3) * 2;
            #pragma unroll
            for (int hh = 0; hh < 2; hh++) {
                size_t p = (size_t)(p0 + mrow + hh * 8);
                size_t idx = (p * HM + col) >> 1;
                uint32_t hu = g_hb[idx];
                float h0 = __uint_as_float(hu << 16);
                float h1 = __uint_as_float(hu & 0xffff0000u);
                float v0 = acc[s][nt][hh * 2 + 0];
                float v1 = acc[s][nt][hh * 2 + 1];
                float r0 = (v0 / (1.f + __expf(-v0))) * h0;
                float r1 = (v1 / (1.f + __expf(-v1))) * h1;
                g_gb[idx] = pk(r0, r1);
            }
        }
    }
}

// ---------------- kernel 6: grouped GEMM2 po = (g @ W2[e] + b2) * w ----------
__global__ void __launch_bounds__(512, 1)
k_gemm2(const float* __restrict__ rW2, const float* __restrict__ sW2,
        const float* __restrict__ rb2, const float* __restrict__ sb2) {
    extern __shared__ uint8_t dyn[];
    uint32_t* Bb = (uint32_t*)(dyn + BOFF);
    float* sPw = (float*)(dyn + XOFF);
    uint32_t saA = cvta(dyn), saB = cvta(Bb);
    int grp = blockIdx.z;
    int start = g_off[grp], cnt = g_off[grp + 1] - start;
    if ((int)blockIdx.x * BMG >= cnt) return;
    const float* W  = (grp < ER) ? rW2 + (size_t)grp * HM * DM
                                 : sW2 + (size_t)(grp - ER) * HM * DM;
    const float* bv = (grp < ER) ? rb2 + (size_t)grp * DM
                                 : sb2 + (size_t)(grp - ER) * DM;
    int nb = blockIdx.y * BNG;
    int tid = threadIdx.x, lane = tid & 31, wid = tid >> 5;
    int warp_m = wid >> 1, warp_n = wid & 1;
    int amf = tid >> 1, ahalf = (tid & 1) * 16;

    for (int mt = blockIdx.x; mt * BMG < cnt; mt += gridDim.x) {
        int m0 = mt * BMG;
        int rem = cnt - m0; if (rem > BMG) rem = BMG;
        bool active = (warp_m * 32 < rem);
        __syncthreads();
        if (tid < BMG) sPw[tid] = (tid < rem) ? g_pw[start + m0 + tid] : 0.f;
        __syncthreads();
        int ar = amf < rem ? amf : (rem - 1);
        const uint32_t* arow = g_gb + (size_t)(start + m0 + ar) * (HM / 2);
        float acc[2][8][4];
        #pragma unroll
        for (int s = 0; s < 2; s++)
            #pragma unroll
            for (int n = 0; n < 8; n++)
                #pragma unroll
                for (int j = 0; j < 4; j++) acc[s][n][j] = 0.f;
        {
            float4 f[4];
            ldB(W, DM, 0, nb, tid, f);
            stB(Bb, tid, f);
            CPA4(saA + (uint32_t)((amf * AST + ahalf) * 4), arow + ahalf);
            CPC(); CPW();
        }
        __syncthreads();
        int buf = 0;
        for (int c = 0; c < HM / BK; c++) {
            float4 f[4];
            bool pre = (c + 1 < HM / BK);
            if (pre) {
                ldB(W, DM, (c + 1) * BK, nb, tid, f);
                CPA4(saA + (buf ^ 1) * ABUF_BYTES + (uint32_t)((amf * AST + ahalf) * 4),
                     arow + (c + 1) * 32 + ahalf);
                CPC();
            }
            if (active)
                mma_chunk(saA + buf * ABUF_BYTES, saB + buf * BBUF_BYTES,
                          acc, warp_m, warp_n, lane);
            if (pre) stB(Bb + (buf ^ 1) * BBUFW, tid, f);
            CPW();
            __syncthreads();
            buf ^= 1;
        }
        if (active) {
            #pragma unroll
            for (int s = 0; s < 2; s++) {
                int mrow = warp_m * 32 + s * 16 + (lane >> 2);
                #pragma unroll
                for (int nt = 0; nt < 8; nt++) {
                    int col = nb + warp_n * 64 + nt * 8 + (lane & 3) * 2;
                    float2 bb = *(const float2*)&bv[col];
                    if (mrow < rem) {
                        size_t p = (size_t)(start + m0 + mrow);
                        float w = sPw[mrow];
                        *(float2*)&g_po[p * DM + col] =
                            make_float2((acc[s][nt][0] + bb.x) * w,
                                        (acc[s][nt][1] + bb.y) * w);
                    }
                    if (mrow + 8 < rem) {
                        size_t p = (size_t)(start + m0 + mrow + 8);
                        float w = sPw[mrow + 8];
                        *(float2*)&g_po[p * DM + col] =
                            make_float2((acc[s][nt][2] + bb.x) * w,
                                        (acc[s][nt][3] + bb.y) * w);
                    }
                }
            }
        }
    }
}

// ---------------- kernel 7: per-token reduce of 8 pair rows ----------------
__global__ void __launch_bounds__(256) k_reduce(float* __restrict__ out) {
    int t = blockIdx.x, tid = threadIdx.x;
    __shared__ int pos[8];
    if (tid < 8) pos[tid] = g_pos[t * 8 + tid];
    __syncthreads();
    size_t d0 = (size_t)tid * 4;
    float4 s = *(float4*)&out[(size_t)t * DM + d0];
    #pragma unroll
    for (int j = 0; j < 8; j++) {
        float4 v = *(const float4*)&g_po[(size_t)pos[j] * DM + d0];
        s.x += v.x; s.y += v.y; s.z += v.z; s.w += v.w;
    }
    *(float4*)&out[(size_t)t * DM + d0] = s;
}

// ---------------- launcher ----------------
extern "C" void kernel_launch(void* const* d_in, const int* in_sizes, int n_in,
                              void* d_out, int out_size) {
    const float* x      = (const float*)d_in[0];
    const float* norm_w = (const float*)d_in[1];
    const float* Wr     = (const float*)d_in[2];
    const float* sW1    = (const float*)d_in[3];
    const float* sb1    = (const float*)d_in[4];
    const float* sW2    = (const float*)d_in[5];
    const float* sb2    = (const float*)d_in[6];
    const float* sWg    = (const float*)d_in[7];
    const float* rW1    = (const float*)d_in[8];
    const float* rb1    = (const float*)d_in[9];
    const float* rW2    = (const float*)d_in[10];
    const float* rb2    = (const float*)d_in[11];
    const float* rWg    = (const float*)d_in[12];
    const float* bias   = (const float*)d_in[13];
    float* out = (float*)d_out;

    cudaFuncSetAttribute(k_gemm1, cudaFuncAttributeMaxDynamicSharedMemorySize, DSMEM);
    cudaFuncSetAttribute(k_gate,  cudaFuncAttributeMaxDynamicSharedMemorySize, DSMEM);
    cudaFuncSetAttribute(k_gemm2, cudaFuncAttributeMaxDynamicSharedMemorySize, DSMEM);

    k_rmsnorm<<<T_TOK, 256>>>(x, norm_w, out);
    k_route<<<T_TOK / 64, 256>>>(Wr, bias);
    k_scatter<<<(NPAIR + 255) / 256, 256>>>();
    k_gemm1<<<dim3(8, HM / BNG, NGRP), 512, DSMEM>>>(rW1, sW1, rb1, sb1);
    k_gate<<<dim3(NPAIR / BMG, HM / BNG), 512, DSMEM>>>(rWg, sWg);
    k_gemm2<<<dim3(8, DM / BNG, NGRP), 512, DSMEM>>>(rW2, sW2, rb2, sb2);
    k_reduce<<<T_TOK, 256>>>(out);
}